// round 16
// baseline (speedup 1.0000x reference)
#include <cuda_runtime.h>
#include <cstdint>

#define NN 50000
#define NE 500000
#define DN 128
#define DE 64
#define KA 256
#define HM 64

__device__ float g_x[NN * DN];
__device__ float g_ea[NE * DE];     // edge state, SORTED-BY-SRC order after layer 0
__device__ float g_agg[NN * DN];
__device__ float g_cnt[NN];
__device__ float g_xw[NN * DN];
__device__ float g_xe[NN * DN];
__device__ int g_scnt[NN];
__device__ int g_cur[NN];
__device__ int g_perm[NE];          // sorted pos -> original edge id
__device__ int g_srcS[NE];          // src sorted (ascending runs)
__device__ int g_dstS[NE];          // dst permuted

// ===================== helpers =====================
__device__ __forceinline__ uint32_t smem_u32(const void* p) {
    uint32_t a;
    asm("{ .reg .u64 t; cvta.to.shared.u64 t, %1; cvt.u32.u64 %0, t; }" : "=r"(a) : "l"(p));
    return a;
}
#define LDSM4(r0, r1, r2, r3, addr) \
    asm volatile("ldmatrix.sync.aligned.m8n8.x4.shared.b16 {%0,%1,%2,%3}, [%4];" \
                 : "=r"(r0), "=r"(r1), "=r"(r2), "=r"(r3) : "r"(addr))
#define MMA(c, a, b) \
    asm volatile("mma.sync.aligned.m16n8k16.row.col.f32.bf16.bf16.f32 " \
                 "{%0,%1,%2,%3},{%4,%5,%6,%7},{%8,%9},{%0,%1,%2,%3};" \
                 : "+f"((c)[0]), "+f"((c)[1]), "+f"((c)[2]), "+f"((c)[3]) \
                 : "r"((a)[0]), "r"((a)[1]), "r"((a)[2]), "r"((a)[3]), \
                   "r"((b)[0]), "r"((b)[1]))
#define BARG(id) asm volatile("bar.sync %0, %1;" :: "r"(id), "r"(256) : "memory")
#define RED2(p, a, b) \
    asm volatile("red.global.add.v2.f32 [%0], {%1, %2};" :: "l"(p), "f"(a), "f"(b) : "memory")

__device__ __forceinline__ void splitp(float a, float b, uint32_t& hi, uint32_t& lo) {
    uint32_t ua = __float_as_uint(a), ub = __float_as_uint(b);
    hi = __byte_perm(ua, ub, 0x7632);
    float la = a - __uint_as_float(ua & 0xFFFF0000u);
    float lb = b - __uint_as_float(ub & 0xFFFF0000u);
    lo = __byte_perm(__float_as_uint(la), __float_as_uint(lb), 0x7632);
}

// ===================== prep: counts + src-sort =====================
__global__ void cnt_kernel(const int* __restrict__ src, const int* __restrict__ dst) {
    int e = blockIdx.x * blockDim.x + threadIdx.x;
    if (e < NE) {
        atomicAdd(&g_cnt[dst[e]], 1.0f);
        atomicAdd(&g_scnt[src[e]], 1);
    }
}

__global__ void scan_kernel() {   // 1 block, 512 threads: exclusive scan of g_scnt
    __shared__ int ssum[512];
    const int t = threadIdx.x;
    const int CH = (NN + 511) / 512;
    int base = t * CH;
    int s = 0;
    for (int i = 0; i < CH; ++i) {
        int idx = base + i;
        if (idx < NN) s += g_scnt[idx];
    }
    ssum[t] = s;
    __syncthreads();
    for (int off = 1; off < 512; off <<= 1) {
        int v = (t >= off) ? ssum[t - off] : 0;
        __syncthreads();
        ssum[t] += v;
        __syncthreads();
    }
    int run = ssum[t] - s;
    for (int i = 0; i < CH; ++i) {
        int idx = base + i;
        if (idx < NN) {
            int c = g_scnt[idx];
            g_cur[idx] = run;
            run += c;
        }
    }
}

__global__ void scatter_kernel(const int* __restrict__ src, const int* __restrict__ dst) {
    int e = blockIdx.x * blockDim.x + threadIdx.x;
    if (e < NE) {
        int s = src[e];
        int pos = atomicAdd(&g_cur[s], 1);
        g_perm[pos] = e;
        g_srcS[pos] = s;
        g_dstS[pos] = dst[e];
    }
}

// ============ NODE BOTH (512 thr, 2 ping-pong groups) ============
#define NB_P 272
#define NB_WE_H 0
#define NB_WE_L 34816
#define NB_WM_H 69632
#define NB_WM_L 104448
#define NB_GRP 139264
#define NB_SMEM 208896

__global__ void __launch_bounds__(512, 1)
node_both(const float* __restrict__ xin, const float* __restrict__ We,
          const float* __restrict__ Wm, int do_e, int do_m,
          float* __restrict__ out_e, float* __restrict__ out_m) {
    extern __shared__ char sm[];
    const uint32_t sb = smem_u32(sm);
    const int t = threadIdx.x, lane = t & 31, wid = t >> 5;
    const int g = wid >> 3, w8 = wid & 7, t8 = t & 255;

    if (do_e) {
        for (int i = t; i < 128 * 64; i += 512) {
            int n = i & 127, kp = i >> 7, k = 2 * kp;
            float w0, w1;
            if (n < 64) { w0 = We[k * 64 + n]; w1 = We[(k + 1) * 64 + n]; }
            else { w0 = We[(128 + k) * 64 + n - 64]; w1 = We[(129 + k) * 64 + n - 64]; }
            uint32_t h, l;
            splitp(w0, w1, h, l);
            *(uint32_t*)(sm + NB_WE_H + n * NB_P + kp * 4) = h;
            *(uint32_t*)(sm + NB_WE_L + n * NB_P + kp * 4) = l;
        }
    }
    if (do_m) {
        for (int i = t; i < 128 * 64; i += 512) {
            int n = i & 127, kp = i >> 7, k = 2 * kp;
            uint32_t h, l;
            splitp(Wm[k * 128 + n], Wm[(k + 1) * 128 + n], h, l);
            *(uint32_t*)(sm + NB_WM_H + n * NB_P + kp * 4) = h;
            *(uint32_t*)(sm + NB_WM_L + n * NB_P + kp * 4) = l;
        }
    }
    __syncthreads();

    const int AH = NB_GRP + g * 34816, AL = AH + 17408;
    const int bar = 1 + g;
    const int we = w8 >> 1, wo = w8 & 1;
    const int am = we * 16 + (lane & 15);
    const int ak = (lane >> 4) << 3;
    const int bn0 = wo * 64 + (lane & 7) + ((lane >> 4) << 3);
    const int bk = (lane & 8) ? 8 : 0;
    const int ntiles = (NN + 63) >> 6;

    for (int tile = blockIdx.x * 2 + g; tile < ntiles; tile += gridDim.x * 2) {
        BARG(bar);
        for (int i = t8; i < 64 * 16; i += 256) {
            int row = i >> 4, gg = i & 15, k0 = gg * 8;
            int nd = (tile << 6) + row;
            uint4 H = make_uint4(0, 0, 0, 0), L = H;
            if (nd < NN) {
                float4 v0 = *(const float4*)(xin + (size_t)nd * DN + k0);
                float4 v1 = *(const float4*)(xin + (size_t)nd * DN + k0 + 4);
                splitp(v0.x, v0.y, H.x, L.x); splitp(v0.z, v0.w, H.y, L.y);
                splitp(v1.x, v1.y, H.z, L.z); splitp(v1.z, v1.w, H.w, L.w);
            }
            *(uint4*)(sm + AH + row * NB_P + gg * 16) = H;
            *(uint4*)(sm + AL + row * NB_P + gg * 16) = L;
        }
        BARG(bar);

        int r0 = we * 16 + (lane >> 2), r1 = r0 + 8;
        int i0 = (tile << 6) + r0, i1 = (tile << 6) + r1;
#pragma unroll
        for (int pass = 0; pass < 2; ++pass) {
            if (pass == 0 && !do_e) continue;
            if (pass == 1 && !do_m) continue;
            const int WH = pass ? NB_WM_H : NB_WE_H;
            const int WL = pass ? NB_WM_L : NB_WE_L;
            float* outp = pass ? out_m : out_e;
            float c[8][4];
#pragma unroll
            for (int n = 0; n < 8; ++n) { c[n][0] = c[n][1] = c[n][2] = c[n][3] = 0.f; }
#pragma unroll
            for (int ks = 0; ks < 8; ++ks) {
                int k0 = ks * 16;
                uint32_t ah[4], al[4];
                uint32_t aoff = am * NB_P + (k0 + ak) * 2;
                LDSM4(ah[0], ah[1], ah[2], ah[3], sb + AH + aoff);
                LDSM4(al[0], al[1], al[2], al[3], sb + AL + aoff);
                uint32_t Bh[8][2], Bl[8][2];
#pragma unroll
                for (int p = 0; p < 4; ++p) {
                    uint32_t boff = (uint32_t)(bn0 + p * 16) * NB_P + (k0 + bk) * 2;
                    LDSM4(Bh[2 * p][0], Bh[2 * p][1], Bh[2 * p + 1][0], Bh[2 * p + 1][1],
                          sb + WH + boff);
                    LDSM4(Bl[2 * p][0], Bl[2 * p][1], Bl[2 * p + 1][0], Bl[2 * p + 1][1],
                          sb + WL + boff);
                }
#pragma unroll
                for (int n = 0; n < 8; ++n) MMA(c[n], ah, Bh[n]);
#pragma unroll
                for (int n = 0; n < 8; ++n) MMA(c[n], ah, Bl[n]);
#pragma unroll
                for (int n = 0; n < 8; ++n) MMA(c[n], al, Bh[n]);
            }
#pragma unroll
            for (int n = 0; n < 8; ++n) {
                int col = wo * 64 + n * 8 + (lane & 3) * 2;
                if (i0 < NN)
                    *(float2*)(outp + (size_t)i0 * DN + col) = make_float2(c[n][0], c[n][1]);
                if (i1 < NN)
                    *(float2*)(outp + (size_t)i1 * DN + col) = make_float2(c[n][2], c[n][3]);
            }
        }
    }
}

// ============ MESSAGE: 512 thr, 2 groups, sorted edges ============
#define MP 144
#define MS_WT_H 0
#define MS_WT_L 18432
#define MS_GRP 36864
#define MS_G_SZ 53248          // AH 9216 | AL 9216 | XW 33792 | ssrc/sdst/sperm 768 + pad
#define MS_BIAS 143360
#define MS_SMEM 143872

__global__ void __launch_bounds__(512, 1)
msg_mma(const float* __restrict__ ea, int use_perm,
        const float* __restrict__ W, const float* __restrict__ bias) {
    extern __shared__ char sm[];
    const uint32_t sb = smem_u32(sm);
    float* bs = (float*)(sm + MS_BIAS);
    const int t = threadIdx.x, lane = t & 31, wid = t >> 5;
    const int g = wid >> 3, w8 = wid & 7, t8 = t & 255;

    for (int i = t; i < 128 * 32; i += 512) {
        int n = i & 127, kp = i >> 7;
        uint32_t h, l;
        splitp(W[(2 * kp) * DN + n], W[(2 * kp + 1) * DN + n], h, l);
        *(uint32_t*)(sm + MS_WT_H + n * MP + kp * 4) = h;
        *(uint32_t*)(sm + MS_WT_L + n * MP + kp * 4) = l;
    }
    if (t < 128) bs[t] = bias[t];
    __syncthreads();

    const int GRP = MS_GRP + g * MS_G_SZ;
    const int AH = GRP, AL = GRP + 9216;
    float* xws = (float*)(sm + GRP + 18432);
    int* ssrc = (int*)(sm + GRP + 52224);
    int* sdst = ssrc + 64;
    int* sperm = ssrc + 128;
    const int bar = 1 + g;

    const int we = w8 >> 1, wo = w8 & 1;
    const int am = we * 16 + (lane & 15);
    const int ak = (lane >> 4) << 3;
    const int bn0 = wo * 64 + (lane & 7) + ((lane >> 4) << 3);
    const int bk = (lane & 8) ? 8 : 0;
    const int ntiles = (NE + 63) >> 6;

    for (int tile = blockIdx.x * 2 + g; tile < ntiles; tile += gridDim.x * 2) {
        BARG(bar);
        if (t8 < 64) {
            int e = tile * 64 + t8;
            bool ok = (e < NE);
            ssrc[t8] = ok ? g_srcS[e] : -1;
            sdst[t8] = ok ? g_dstS[e] : -1;
            sperm[t8] = ok ? (use_perm ? g_perm[e] : e) : 0;
        }
        BARG(bar);
        for (int i = t8; i < 64 * 8; i += 256) {
            int row = i >> 3, gg = i & 7, k0 = gg * 8;
            uint4 H = make_uint4(0, 0, 0, 0), L = H;
            if (ssrc[row] >= 0) {
                int ep = sperm[row];
                float4 v0 = *(const float4*)(ea + (size_t)ep * DE + k0);
                float4 v1 = *(const float4*)(ea + (size_t)ep * DE + k0 + 4);
                splitp(v0.x, v0.y, H.x, L.x); splitp(v0.z, v0.w, H.y, L.y);
                splitp(v1.x, v1.y, H.z, L.z); splitp(v1.z, v1.w, H.w, L.w);
            }
            *(uint4*)(sm + AH + row * MP + gg * 16) = H;
            *(uint4*)(sm + AL + row * MP + gg * 16) = L;
        }
        for (int i = t8; i < 64 * 32; i += 256) {
            int row = i >> 5, q = i & 31;
            int s = ssrc[row];
            if (s >= 0)
                *(float4*)(xws + row * 132 + q * 4) =
                    *(const float4*)(g_xw + (size_t)s * DN + q * 4);
        }
        BARG(bar);

        float c[8][4];
#pragma unroll
        for (int n = 0; n < 8; ++n) { c[n][0] = c[n][1] = c[n][2] = c[n][3] = 0.f; }
#pragma unroll
        for (int ks = 0; ks < 4; ++ks) {
            int k0 = ks * 16;
            uint32_t ah[4], al[4];
            uint32_t aoff = am * MP + (k0 + ak) * 2;
            LDSM4(ah[0], ah[1], ah[2], ah[3], sb + AH + aoff);
            LDSM4(al[0], al[1], al[2], al[3], sb + AL + aoff);
            uint32_t Bh[8][2], Bl[8][2];
#pragma unroll
            for (int p = 0; p < 4; ++p) {
                uint32_t boff = (uint32_t)(bn0 + p * 16) * MP + (k0 + bk) * 2;
                LDSM4(Bh[2 * p][0], Bh[2 * p][1], Bh[2 * p + 1][0], Bh[2 * p + 1][1],
                      sb + MS_WT_H + boff);
                LDSM4(Bl[2 * p][0], Bl[2 * p][1], Bl[2 * p + 1][0], Bl[2 * p + 1][1],
                      sb + MS_WT_L + boff);
            }
#pragma unroll
            for (int n = 0; n < 8; ++n) MMA(c[n], ah, Bh[n]);
#pragma unroll
            for (int n = 0; n < 8; ++n) MMA(c[n], ah, Bl[n]);
#pragma unroll
            for (int n = 0; n < 8; ++n) MMA(c[n], al, Bh[n]);
        }
        int r0 = we * 16 + (lane >> 2), r1 = r0 + 8;
        int d0 = sdst[r0], d1 = sdst[r1];
#pragma unroll
        for (int n = 0; n < 8; ++n) {
            int col = wo * 64 + n * 8 + (lane & 3) * 2;
            float b0 = bs[col], b1 = bs[col + 1];
            if (d0 >= 0) {
                float v0 = fmaxf(c[n][0] + xws[r0 * 132 + col] + b0, 0.f);
                float v1 = fmaxf(c[n][1] + xws[r0 * 132 + col + 1] + b1, 0.f);
                if (v0 > 0.f || v1 > 0.f)
                    RED2(g_agg + (size_t)d0 * DN + col, v0, v1);
            }
            if (d1 >= 0) {
                float v0 = fmaxf(c[n][2] + xws[r1 * 132 + col] + b0, 0.f);
                float v1 = fmaxf(c[n][3] + xws[r1 * 132 + col + 1] + b1, 0.f);
                if (v0 > 0.f || v1 > 0.f)
                    RED2(g_agg + (size_t)d1 * DN + col, v0, v1);
            }
        }
    }
}

// ============ EDGE: 256 thr, 3 blocks/SM, sorted edges ============
#define EP 144
#define ED_WT_H 0
#define ED_WT_L 9216
#define ED_A_H 18432
#define ED_A_L 27648
#define ED_XE1 36864
#define ED_XE2 54272
#define ED_IDX 71680           // ssrc 64 | sdst 64 | sperm 64 (768 B)
#define ED_BIAS 72448
#define ED_SMEM 72704

__global__ void __launch_bounds__(256, 1)
edge_mma(const float* __restrict__ ea, int use_perm,
         const float* __restrict__ W, const float* __restrict__ bias,
         float* __restrict__ ea_out) {
    extern __shared__ char sm[];
    const uint32_t sb = smem_u32(sm);
    float* bs = (float*)(sm + ED_BIAS);
    float* xe1s = (float*)(sm + ED_XE1);
    float* xe2s = (float*)(sm + ED_XE2);
    int* ssrc = (int*)(sm + ED_IDX);
    int* sdst = ssrc + 64;
    int* sperm = ssrc + 128;
    const int t = threadIdx.x, lane = t & 31, wid = t >> 5;

    for (int i = t; i < 64 * 32; i += 256) {
        int n = i & 63, kp = i >> 6;
        uint32_t h, l;
        splitp(W[(2 * kp) * DE + n], W[(2 * kp + 1) * DE + n], h, l);
        *(uint32_t*)(sm + ED_WT_H + n * EP + kp * 4) = h;
        *(uint32_t*)(sm + ED_WT_L + n * EP + kp * 4) = l;
    }
    if (t < 64) bs[t] = bias[t];

    const int we = wid >> 1, wo = wid & 1;
    const int am = we * 16 + (lane & 15);
    const int ak = (lane >> 4) << 3;
    const int bn0 = wo * 32 + (lane & 7) + ((lane >> 4) << 3);
    const int bk = (lane & 8) ? 8 : 0;
    const int ntiles = (NE + 63) >> 6;

    for (int tile = blockIdx.x; tile < ntiles; tile += gridDim.x) {
        __syncthreads();
        if (t < 64) {
            int e = tile * 64 + t;
            bool ok = (e < NE);
            ssrc[t] = ok ? g_srcS[e] : -1;
            sdst[t] = ok ? g_dstS[e] : -1;
            sperm[t] = ok ? (use_perm ? g_perm[e] : e) : 0;
        }
        __syncthreads();
        for (int i = t; i < 64 * 8; i += 256) {
            int row = i >> 3, gg = i & 7, k0 = gg * 8;
            uint4 H = make_uint4(0, 0, 0, 0), L = H;
            if (ssrc[row] >= 0) {
                int ep = sperm[row];
                float4 v0 = *(const float4*)(ea + (size_t)ep * DE + k0);
                float4 v1 = *(const float4*)(ea + (size_t)ep * DE + k0 + 4);
                splitp(v0.x, v0.y, H.x, L.x); splitp(v0.z, v0.w, H.y, L.y);
                splitp(v1.x, v1.y, H.z, L.z); splitp(v1.z, v1.w, H.w, L.w);
            }
            *(uint4*)(sm + ED_A_H + row * EP + gg * 16) = H;
            *(uint4*)(sm + ED_A_L + row * EP + gg * 16) = L;
        }
        __syncthreads();
        for (int i = t; i < 64 * 16; i += 256) {
            int row = i >> 4, q = i & 15;
            int s = ssrc[row], d = sdst[row];
            if (s >= 0) {
                *(float4*)(xe1s + row * 68 + q * 4) =
                    *(const float4*)(g_xe + (size_t)s * DN + q * 4);
                *(float4*)(xe2s + row * 68 + q * 4) =
                    *(const float4*)(g_xe + (size_t)d * DN + 64 + q * 4);
            }
        }
        __syncthreads();

        float c[4][4];
#pragma unroll
        for (int n = 0; n < 4; ++n) { c[n][0] = c[n][1] = c[n][2] = c[n][3] = 0.f; }
#pragma unroll
        for (int ks = 0; ks < 4; ++ks) {
            int k0 = ks * 16;
            uint32_t ah[4], al[4];
            uint32_t aoff = am * EP + (k0 + ak) * 2;
            LDSM4(ah[0], ah[1], ah[2], ah[3], sb + ED_A_H + aoff);
            LDSM4(al[0], al[1], al[2], al[3], sb + ED_A_L + aoff);
            uint32_t Bh[4][2], Bl[4][2];
#pragma unroll
            for (int p = 0; p < 2; ++p) {
                uint32_t boff = (uint32_t)(bn0 + p * 16) * EP + (k0 + bk) * 2;
                LDSM4(Bh[2 * p][0], Bh[2 * p][1], Bh[2 * p + 1][0], Bh[2 * p + 1][1],
                      sb + ED_WT_H + boff);
                LDSM4(Bl[2 * p][0], Bl[2 * p][1], Bl[2 * p + 1][0], Bl[2 * p + 1][1],
                      sb + ED_WT_L + boff);
            }
#pragma unroll
            for (int n = 0; n < 4; ++n) MMA(c[n], ah, Bh[n]);
#pragma unroll
            for (int n = 0; n < 4; ++n) MMA(c[n], ah, Bl[n]);
#pragma unroll
            for (int n = 0; n < 4; ++n) MMA(c[n], al, Bh[n]);
        }
        int r0 = we * 16 + (lane >> 2), r1 = r0 + 8;
        int e0 = tile * 64 + r0, e1 = tile * 64 + r1;
#pragma unroll
        for (int n = 0; n < 4; ++n) {
            int col = wo * 32 + n * 8 + (lane & 3) * 2;
            float b0 = bs[col], b1 = bs[col + 1];
            if (e0 < NE) {
                float2 v = make_float2(
                    fmaxf(c[n][0] + xe1s[r0 * 68 + col] + xe2s[r0 * 68 + col] + b0, 0.f),
                    fmaxf(c[n][1] + xe1s[r0 * 68 + col + 1] + xe2s[r0 * 68 + col + 1] + b1, 0.f));
                *(float2*)(ea_out + (size_t)e0 * DE + col) = v;   // sorted position
            }
            if (e1 < NE) {
                float2 v = make_float2(
                    fmaxf(c[n][2] + xe1s[r1 * 68 + col] + xe2s[r1 * 68 + col] + b0, 0.f),
                    fmaxf(c[n][3] + xe1s[r1 * 68 + col + 1] + xe2s[r1 * 68 + col + 1] + b1, 0.f));
                *(float2*)(ea_out + (size_t)e1 * DE + col) = v;
            }
        }
    }
}

// ============ UPDATE (mma, 512 thr split-K) ============
#define UP_P 528
#define UP_WT_H 0
#define UP_WT_L 67584
#define UP_A 135168
#define UP_BIAS 202752
#define UP_SINV 203264
#define UP_SSQ 203520
#define UP_SMEM 204032

__global__ void __launch_bounds__(512, 1)
upd_mma(const float* __restrict__ xin,
        const float* __restrict__ W, const float* __restrict__ bias) {
    extern __shared__ char sm[];
    const uint32_t sb = smem_u32(sm);
    float* bs = (float*)(sm + UP_BIAS);
    float* sinv = (float*)(sm + UP_SINV);
    float* ssq = (float*)(sm + UP_SSQ);
    float* P = (float*)(sm + UP_A);
    const int t = threadIdx.x, lane = t & 31, wid = t >> 5;
    const int wk = wid >> 3, w8 = wid & 7;

    for (int i = t; i < 128 * 128; i += 512) {
        int n = i & 127, kp = i >> 7;
        uint32_t h, l;
        splitp(W[(2 * kp) * DN + n], W[(2 * kp + 1) * DN + n], h, l);
        *(uint32_t*)(sm + UP_WT_H + n * UP_P + kp * 4) = h;
        *(uint32_t*)(sm + UP_WT_L + n * UP_P + kp * 4) = l;
    }
    if (t < 128) bs[t] = bias[t];

    const int we = w8 >> 1, wo = w8 & 1;
    const int am = we * 16 + (lane & 15);
    const int ak = (lane >> 4) << 3;
    const int bn0 = wo * 64 + (lane & 7) + ((lane >> 4) << 3);
    const int bk = (lane & 8) ? 8 : 0;
    const int ntiles = (NN + 63) >> 6;

    for (int tile = blockIdx.x; tile < ntiles; tile += gridDim.x) {
        __syncthreads();
        if (t < 64) {
            int i = (tile << 6) + t;
            float c = (i < NN) ? g_cnt[i] : 1.f;
            sinv[t] = 1.f / fmaxf(c, 1.f);
        }
        __syncthreads();
        for (int i = t; i < 64 * 32; i += 512) {
            int row = i >> 5, gg = i & 31, k0 = gg * 8;
            int nd = (tile << 6) + row;
            uint4 H = make_uint4(0, 0, 0, 0), L = H;
            if (nd < NN) {
                float4 v0, v1;
                if (k0 < DN) {
                    float iv = sinv[row];
                    v0 = *(const float4*)(g_agg + (size_t)nd * DN + k0);
                    v1 = *(const float4*)(g_agg + (size_t)nd * DN + k0 + 4);
                    v0.x *= iv; v0.y *= iv; v0.z *= iv; v0.w *= iv;
                    v1.x *= iv; v1.y *= iv; v1.z *= iv; v1.w *= iv;
                } else {
                    v0 = *(const float4*)(xin + (size_t)nd * DN + (k0 - DN));
                    v1 = *(const float4*)(xin + (size_t)nd * DN + (k0 - DN) + 4);
                }
                splitp(v0.x, v0.y, H.x, L.x); splitp(v0.z, v0.w, H.y, L.y);
                splitp(v1.x, v1.y, H.z, L.z); splitp(v1.z, v1.w, H.w, L.w);
            }
            *(uint4*)(sm + UP_A + row * UP_P + gg * 16) = H;
            *(uint4*)(sm + UP_A + 33792 + row * UP_P + gg * 16) = L;
        }
        __syncthreads();

        float c[8][4];
#pragma unroll
        for (int n = 0; n < 8; ++n) { c[n][0] = c[n][1] = c[n][2] = c[n][3] = 0.f; }
#pragma unroll
        for (int j = 0; j < 8; ++j) {
            int k0 = (wk * 8 + j) * 16;
            uint32_t ah[4], al[4];
            uint32_t aoff = am * UP_P + (k0 + ak) * 2;
            LDSM4(ah[0], ah[1], ah[2], ah[3], sb + UP_A + aoff);
            LDSM4(al[0], al[1], al[2], al[3], sb + UP_A + 33792 + aoff);
            uint32_t Bh[8][2], Bl[8][2];
#pragma unroll
            for (int p = 0; p < 4; ++p) {
                uint32_t boff = (uint32_t)(bn0 + p * 16) * UP_P + (k0 + bk) * 2;
                LDSM4(Bh[2 * p][0], Bh[2 * p][1], Bh[2 * p + 1][0], Bh[2 * p + 1][1],
                      sb + UP_WT_H + boff);
                LDSM4(Bl[2 * p][0], Bl[2 * p][1], Bl[2 * p + 1][0], Bl[2 * p + 1][1],
                      sb + UP_WT_L + boff);
            }
#pragma unroll
            for (int n = 0; n < 8; ++n) MMA(c[n], ah, Bh[n]);
#pragma unroll
            for (int n = 0; n < 8; ++n) MMA(c[n], ah, Bl[n]);
#pragma unroll
            for (int n = 0; n < 8; ++n) MMA(c[n], al, Bh[n]);
        }
        __syncthreads();
        int r0 = we * 16 + (lane >> 2), r1 = r0 + 8;
        if (wk == 0) {
#pragma unroll
            for (int n = 0; n < 8; ++n) {
                int col = wo * 64 + n * 8 + (lane & 3) * 2;
                *(float2*)(P + r0 * 128 + col) = make_float2(c[n][0], c[n][1]);
                *(float2*)(P + r1 * 128 + col) = make_float2(c[n][2], c[n][3]);
            }
        }
        __syncthreads();
        if (wk == 1) {
            float s0 = 0.f, s1 = 0.f;
#pragma unroll
            for (int n = 0; n < 8; ++n) {
                int col = wo * 64 + n * 8 + (lane & 3) * 2;
                float b0 = bs[col], b1 = bs[col + 1];
                float2 p0 = *(float2*)(P + r0 * 128 + col);
                float2 p1 = *(float2*)(P + r1 * 128 + col);
                c[n][0] = fmaxf(c[n][0] + p0.x + b0, 0.f);
                c[n][1] = fmaxf(c[n][1] + p0.y + b1, 0.f);
                c[n][2] = fmaxf(c[n][2] + p1.x + b0, 0.f);
                c[n][3] = fmaxf(c[n][3] + p1.y + b1, 0.f);
                s0 += c[n][0] * c[n][0] + c[n][1] * c[n][1];
                s1 += c[n][2] * c[n][2] + c[n][3] * c[n][3];
            }
            s0 += __shfl_xor_sync(0xffffffffu, s0, 1);
            s0 += __shfl_xor_sync(0xffffffffu, s0, 2);
            s1 += __shfl_xor_sync(0xffffffffu, s1, 1);
            s1 += __shfl_xor_sync(0xffffffffu, s1, 2);
            if ((lane & 3) == 0) {
                ssq[wo * 64 + r0] = s0;
                ssq[wo * 64 + r1] = s1;
            }
        }
        __syncthreads();
        if (wk == 1) {
            float sc0 = 1.f / fmaxf(sqrtf(ssq[r0] + ssq[64 + r0]), 1e-12f);
            float sc1 = 1.f / fmaxf(sqrtf(ssq[r1] + ssq[64 + r1]), 1e-12f);
            int i0 = (tile << 6) + r0, i1 = (tile << 6) + r1;
#pragma unroll
            for (int n = 0; n < 8; ++n) {
                int col = wo * 64 + n * 8 + (lane & 3) * 2;
                if (i0 < NN)
                    *(float2*)(g_x + (size_t)i0 * DN + col) =
                        make_float2(c[n][0] * sc0, c[n][1] * sc0);
                if (i1 < NN)
                    *(float2*)(g_x + (size_t)i1 * DN + col) =
                        make_float2(c[n][2] * sc1, c[n][3] * sc1);
            }
        }
    }
}

// ===================== HEAD (SIMT, 256 thr, R12-proven) =====================
__global__ void __launch_bounds__(256, 1)
head_kernel(const float* __restrict__ W1, const float* __restrict__ b1,
            const float* __restrict__ W2, const float* __restrict__ b2,
            float* __restrict__ out) {
    extern __shared__ float smf[];
    float* W1s = smf;
    float* b1s = W1s + DN * HM;
    float* W2s = b1s + HM;
    float* b2s = W2s + HM * DN;
    float* ins = b2s + DN;
    float* hs = ins + 32 * DN;
    const int t = threadIdx.x;
    for (int i = t; i < DN * HM; i += 256) W1s[i] = W1[i];
    for (int i = t; i < HM * DN; i += 256) W2s[i] = W2[i];
    if (t < HM) b1s[t] = b1[t];
    if (t < DN) b2s[t] = b2[t];
    const int tx1 = t & 15, ty1 = t >> 4;
    const int tx2 = t & 31, ty2 = t >> 5;
    const int ntiles = (NN + 31) >> 5;
    for (int tile = blockIdx.x; tile < ntiles; tile += gridDim.x) {
        __syncthreads();
        for (int idx = t; idx < 32 * DN; idx += 256) {
            int it = idx >> 7, c = idx & 127;
            int i = (tile << 5) + it;
            ins[idx] = (i < NN) ? g_x[(size_t)i * DN + c] : 0.f;
        }
        __syncthreads();
        {
            float acc[2][4] = {{0, 0, 0, 0}, {0, 0, 0, 0}};
            const float* inp = ins + (ty1 * 2) * DN;
#pragma unroll 2
            for (int k = 0; k < DN; ++k) {
                float4 w = *(const float4*)(W1s + k * HM + 4 * tx1);
                float v0 = inp[k], v1 = inp[DN + k];
                acc[0][0] += v0 * w.x; acc[0][1] += v0 * w.y;
                acc[0][2] += v0 * w.z; acc[0][3] += v0 * w.w;
                acc[1][0] += v1 * w.x; acc[1][1] += v1 * w.y;
                acc[1][2] += v1 * w.z; acc[1][3] += v1 * w.w;
            }
#pragma unroll
            for (int jj = 0; jj < 2; ++jj) {
                int it = ty1 * 2 + jj;
#pragma unroll
                for (int c = 0; c < 4; ++c)
                    hs[it * HM + 4 * tx1 + c] = fmaxf(acc[jj][c] + b1s[4 * tx1 + c], 0.f);
            }
        }
        __syncthreads();
        {
            float acc[4][4];
#pragma unroll
            for (int ii = 0; ii < 4; ++ii)
#pragma unroll
                for (int c = 0; c < 4; ++c) acc[ii][c] = 0.f;
            const float* inp = hs + (ty2 * 4) * HM;
#pragma unroll 2
            for (int k = 0; k < HM; ++k) {
                float4 w = *(const float4*)(W2s + k * DN + 4 * tx2);
#pragma unroll
                for (int ii = 0; ii < 4; ++ii) {
                    float v = inp[ii * HM + k];
                    acc[ii][0] += v * w.x; acc[ii][1] += v * w.y;
                    acc[ii][2] += v * w.z; acc[ii][3] += v * w.w;
                }
            }
#pragma unroll
            for (int ii = 0; ii < 4; ++ii) {
                int i = (tile << 5) + ty2 * 4 + ii;
                if (i < NN) {
                    float* o = out + (size_t)i * DN + 4 * tx2;
#pragma unroll
                    for (int c = 0; c < 4; ++c) o[c] = acc[ii][c] + b2s[4 * tx2 + c];
                }
            }
        }
    }
}

// ===================== launch =====================
extern "C" void kernel_launch(void* const* d_in, const int* in_sizes, int n_in,
                              void* d_out, int out_size) {
    (void)in_sizes; (void)n_in; (void)out_size;
    const float* x  = (const float*)d_in[0];
    const float* ea = (const float*)d_in[1];
    const int*   ei = (const int*)d_in[2];
    const float* Wm = (const float*)d_in[3];
    const float* bm = (const float*)d_in[4];
    const float* Wa = (const float*)d_in[5];
    const float* ba = (const float*)d_in[6];
    const float* We = (const float*)d_in[7];
    const float* be = (const float*)d_in[8];
    const float* W1 = (const float*)d_in[9];
    const float* b1 = (const float*)d_in[10];
    const float* W2 = (const float*)d_in[11];
    const float* b2 = (const float*)d_in[12];
    float* out = (float*)d_out;
    const int* src = ei;
    const int* dst = ei + NE;

    int nsm = 0;
    cudaDeviceGetAttribute(&nsm, cudaDevAttrMultiProcessorCount, 0);
    if (nsm <= 0) nsm = 148;

    const int SM_HED = (DN * HM + HM + HM * DN + DN + 32 * DN + 32 * HM) * 4;

    cudaFuncSetAttribute(node_both, cudaFuncAttributeMaxDynamicSharedMemorySize, NB_SMEM);
    cudaFuncSetAttribute(msg_mma,  cudaFuncAttributeMaxDynamicSharedMemorySize, MS_SMEM);
    cudaFuncSetAttribute(edge_mma, cudaFuncAttributeMaxDynamicSharedMemorySize, ED_SMEM);
    cudaFuncSetAttribute(upd_mma,  cudaFuncAttributeMaxDynamicSharedMemorySize, UP_SMEM);
    cudaFuncSetAttribute(head_kernel, cudaFuncAttributeMaxDynamicSharedMemorySize, SM_HED);

    void *agg_addr = 0, *cnt_addr = 0, *scnt_addr = 0, *x_addr = 0, *ea_addr = 0;
    void *xw_addr = 0, *xe_addr = 0;
    cudaGetSymbolAddress(&agg_addr, g_agg);
    cudaGetSymbolAddress(&cnt_addr, g_cnt);
    cudaGetSymbolAddress(&scnt_addr, g_scnt);
    cudaGetSymbolAddress(&x_addr, g_x);
    cudaGetSymbolAddress(&ea_addr, g_ea);
    cudaGetSymbolAddress(&xw_addr, g_xw);
    cudaGetSymbolAddress(&xe_addr, g_xe);

    cudaMemsetAsync(cnt_addr, 0, NN * sizeof(float));
    cudaMemsetAsync(scnt_addr, 0, NN * sizeof(int));
    cnt_kernel<<<(NE + 255) / 256, 256>>>(src, dst);
    scan_kernel<<<1, 512>>>();
    scatter_kernel<<<(NE + 255) / 256, 256>>>(src, dst);

    node_both<<<nsm, 512, NB_SMEM>>>(x, We, Wm, 0, 1,
                                     (float*)xe_addr, (float*)xw_addr);

    for (int l = 0; l < 3; ++l) {
        const float* xl  = (l == 0) ? x  : (const float*)x_addr;
        const float* eal = (l == 0) ? ea : (const float*)ea_addr;
        const float* Wml = Wm + (size_t)l * (DN + DE) * DN;
        const float* Wel = We + (size_t)l * (2 * DN + DE) * DE;
        const float* Wmn = (l < 2) ? Wm + (size_t)(l + 1) * (DN + DE) * DN : Wm;
        int up = (l == 0) ? 1 : 0;
        cudaMemsetAsync(agg_addr, 0, (size_t)NN * DN * sizeof(float));
        msg_mma<<<nsm, 512, MS_SMEM>>>(eal, up, Wml + 128 * DN, bm + l * DN);
        upd_mma<<<nsm, 512, UP_SMEM>>>(xl, Wa + (size_t)l * KA * DN, ba + l * DN);
        node_both<<<nsm, 512, NB_SMEM>>>((const float*)x_addr, Wel, Wmn,
                                         1, (l < 2) ? 1 : 0,
                                         (float*)xe_addr, (float*)xw_addr);
        edge_mma<<<3 * nsm, 256, ED_SMEM>>>(eal, up, Wel + 256 * DE, be + l * DE,
                                            (float*)ea_addr);
    }
    head_kernel<<<nsm, 256, SM_HED>>>(W1, b1, W2, b2, out);
}

// round 17
// speedup vs baseline: 1.0615x; 1.0615x over previous
#include <cuda_runtime.h>
#include <cstdint>

#define NN 50000
#define NE 500000
#define DN 128
#define DE 64
#define KA 256
#define HM 64

__device__ float g_x[NN * DN];
__device__ float g_ea[NE * DE];
__device__ float g_agg[NN * DN];
__device__ float g_cnt[NN];
__device__ float g_xw[NN * DN];   // x @ Wm[0:128]
__device__ float g_xe[NN * DN];   // x @ [We[0:128] | We[128:256]]

// ===================== helpers =====================
__device__ __forceinline__ uint32_t smem_u32(const void* p) {
    uint32_t a;
    asm("{ .reg .u64 t; cvta.to.shared.u64 t, %1; cvt.u32.u64 %0, t; }" : "=r"(a) : "l"(p));
    return a;
}
#define LDSM4(r0, r1, r2, r3, addr) \
    asm volatile("ldmatrix.sync.aligned.m8n8.x4.shared.b16 {%0,%1,%2,%3}, [%4];" \
                 : "=r"(r0), "=r"(r1), "=r"(r2), "=r"(r3) : "r"(addr))
#define MMA(c, a, b) \
    asm volatile("mma.sync.aligned.m16n8k16.row.col.f32.bf16.bf16.f32 " \
                 "{%0,%1,%2,%3},{%4,%5,%6,%7},{%8,%9},{%0,%1,%2,%3};" \
                 : "+f"((c)[0]), "+f"((c)[1]), "+f"((c)[2]), "+f"((c)[3]) \
                 : "r"((a)[0]), "r"((a)[1]), "r"((a)[2]), "r"((a)[3]), \
                   "r"((b)[0]), "r"((b)[1]))
#define BARG(id) asm volatile("bar.sync %0, %1;" :: "r"(id), "r"(256) : "memory")
#define RED2(p, a, b) \
    asm volatile("red.global.add.v2.f32 [%0], {%1, %2};" :: "l"(p), "f"(a), "f"(b) : "memory")

__device__ __forceinline__ void splitp(float a, float b, uint32_t& hi, uint32_t& lo) {
    uint32_t ua = __float_as_uint(a), ub = __float_as_uint(b);
    hi = __byte_perm(ua, ub, 0x7632);
    float la = a - __uint_as_float(ua & 0xFFFF0000u);
    float lb = b - __uint_as_float(ub & 0xFFFF0000u);
    lo = __byte_perm(__float_as_uint(la), __float_as_uint(lb), 0x7632);
}

// ===================== cnt =====================
__global__ void cnt_kernel(const int* __restrict__ dst) {
    int e = blockIdx.x * blockDim.x + threadIdx.x;
    if (e < NE) atomicAdd(&g_cnt[dst[e]], 1.0f);
}

// ============ NODE BOTH (512 thr, 2 ping-pong groups) ============
#define NB_P 272
#define NB_WE_H 0
#define NB_WE_L 34816
#define NB_WM_H 69632
#define NB_WM_L 104448
#define NB_GRP 139264
#define NB_SMEM 208896

__global__ void __launch_bounds__(512, 1)
node_both(const float* __restrict__ xin, const float* __restrict__ We,
          const float* __restrict__ Wm, int do_e, int do_m,
          float* __restrict__ out_e, float* __restrict__ out_m) {
    extern __shared__ char sm[];
    const uint32_t sb = smem_u32(sm);
    const int t = threadIdx.x, lane = t & 31, wid = t >> 5;
    const int g = wid >> 3, w8 = wid & 7, t8 = t & 255;

    if (do_e) {
        for (int i = t; i < 128 * 64; i += 512) {
            int n = i & 127, kp = i >> 7, k = 2 * kp;
            float w0, w1;
            if (n < 64) { w0 = We[k * 64 + n]; w1 = We[(k + 1) * 64 + n]; }
            else { w0 = We[(128 + k) * 64 + n - 64]; w1 = We[(129 + k) * 64 + n - 64]; }
            uint32_t h, l;
            splitp(w0, w1, h, l);
            *(uint32_t*)(sm + NB_WE_H + n * NB_P + kp * 4) = h;
            *(uint32_t*)(sm + NB_WE_L + n * NB_P + kp * 4) = l;
        }
    }
    if (do_m) {
        for (int i = t; i < 128 * 64; i += 512) {
            int n = i & 127, kp = i >> 7, k = 2 * kp;
            uint32_t h, l;
            splitp(Wm[k * 128 + n], Wm[(k + 1) * 128 + n], h, l);
            *(uint32_t*)(sm + NB_WM_H + n * NB_P + kp * 4) = h;
            *(uint32_t*)(sm + NB_WM_L + n * NB_P + kp * 4) = l;
        }
    }
    __syncthreads();

    const int AH = NB_GRP + g * 34816, AL = AH + 17408;
    const int bar = 1 + g;
    const int we = w8 >> 1, wo = w8 & 1;
    const int am = we * 16 + (lane & 15);
    const int ak = (lane >> 4) << 3;
    const int bn0 = wo * 64 + (lane & 7) + ((lane >> 4) << 3);
    const int bk = (lane & 8) ? 8 : 0;
    const int ntiles = (NN + 63) >> 6;

    for (int tile = blockIdx.x * 2 + g; tile < ntiles; tile += gridDim.x * 2) {
        BARG(bar);
        for (int i = t8; i < 64 * 16; i += 256) {
            int row = i >> 4, gg = i & 15, k0 = gg * 8;
            int nd = (tile << 6) + row;
            uint4 H = make_uint4(0, 0, 0, 0), L = H;
            if (nd < NN) {
                float4 v0 = *(const float4*)(xin + (size_t)nd * DN + k0);
                float4 v1 = *(const float4*)(xin + (size_t)nd * DN + k0 + 4);
                splitp(v0.x, v0.y, H.x, L.x); splitp(v0.z, v0.w, H.y, L.y);
                splitp(v1.x, v1.y, H.z, L.z); splitp(v1.z, v1.w, H.w, L.w);
            }
            *(uint4*)(sm + AH + row * NB_P + gg * 16) = H;
            *(uint4*)(sm + AL + row * NB_P + gg * 16) = L;
        }
        BARG(bar);

        int r0 = we * 16 + (lane >> 2), r1 = r0 + 8;
        int i0 = (tile << 6) + r0, i1 = (tile << 6) + r1;
#pragma unroll
        for (int pass = 0; pass < 2; ++pass) {
            if (pass == 0 && !do_e) continue;
            if (pass == 1 && !do_m) continue;
            const int WH = pass ? NB_WM_H : NB_WE_H;
            const int WL = pass ? NB_WM_L : NB_WE_L;
            float* outp = pass ? out_m : out_e;
            float c[8][4];
#pragma unroll
            for (int n = 0; n < 8; ++n) { c[n][0] = c[n][1] = c[n][2] = c[n][3] = 0.f; }
#pragma unroll
            for (int ks = 0; ks < 8; ++ks) {
                int k0 = ks * 16;
                uint32_t ah[4], al[4];
                uint32_t aoff = am * NB_P + (k0 + ak) * 2;
                LDSM4(ah[0], ah[1], ah[2], ah[3], sb + AH + aoff);
                LDSM4(al[0], al[1], al[2], al[3], sb + AL + aoff);
                uint32_t Bh[8][2], Bl[8][2];
#pragma unroll
                for (int p = 0; p < 4; ++p) {
                    uint32_t boff = (uint32_t)(bn0 + p * 16) * NB_P + (k0 + bk) * 2;
                    LDSM4(Bh[2 * p][0], Bh[2 * p][1], Bh[2 * p + 1][0], Bh[2 * p + 1][1],
                          sb + WH + boff);
                    LDSM4(Bl[2 * p][0], Bl[2 * p][1], Bl[2 * p + 1][0], Bl[2 * p + 1][1],
                          sb + WL + boff);
                }
#pragma unroll
                for (int n = 0; n < 8; ++n) MMA(c[n], ah, Bh[n]);
#pragma unroll
                for (int n = 0; n < 8; ++n) MMA(c[n], ah, Bl[n]);
#pragma unroll
                for (int n = 0; n < 8; ++n) MMA(c[n], al, Bh[n]);
            }
#pragma unroll
            for (int n = 0; n < 8; ++n) {
                int col = wo * 64 + n * 8 + (lane & 3) * 2;
                if (i0 < NN)
                    *(float2*)(outp + (size_t)i0 * DN + col) = make_float2(c[n][0], c[n][1]);
                if (i1 < NN)
                    *(float2*)(outp + (size_t)i1 * DN + col) = make_float2(c[n][2], c[n][3]);
            }
        }
    }
}

// ============ MESSAGE: 512 thr, 2 groups, xws staged (R12-proven) ============
#define MP 144
#define MS_WT_H 0
#define MS_WT_L 18432
#define MS_GRP 36864
#define MS_G_SZ 52736
#define MS_BIAS 142336
#define MS_SMEM 142848

__global__ void __launch_bounds__(512, 1)
msg_mma(const float* __restrict__ ea,
        const int* __restrict__ src, const int* __restrict__ dst,
        const float* __restrict__ W, const float* __restrict__ bias) {
    extern __shared__ char sm[];
    const uint32_t sb = smem_u32(sm);
    float* bs = (float*)(sm + MS_BIAS);
    const int t = threadIdx.x, lane = t & 31, wid = t >> 5;
    const int g = wid >> 3, w8 = wid & 7, t8 = t & 255;

    for (int i = t; i < 128 * 32; i += 512) {
        int n = i & 127, kp = i >> 7;
        uint32_t h, l;
        splitp(W[(2 * kp) * DN + n], W[(2 * kp + 1) * DN + n], h, l);
        *(uint32_t*)(sm + MS_WT_H + n * MP + kp * 4) = h;
        *(uint32_t*)(sm + MS_WT_L + n * MP + kp * 4) = l;
    }
    if (t < 128) bs[t] = bias[t];
    __syncthreads();

    const int GRP = MS_GRP + g * MS_G_SZ;
    const int AH = GRP, AL = GRP + 9216;
    float* xws = (float*)(sm + GRP + 18432);
    int* ssrc = (int*)(sm + GRP + 52224);
    int* sdst = ssrc + 64;
    const int bar = 1 + g;

    const int we = w8 >> 1, wo = w8 & 1;
    const int am = we * 16 + (lane & 15);
    const int ak = (lane >> 4) << 3;
    const int bn0 = wo * 64 + (lane & 7) + ((lane >> 4) << 3);
    const int bk = (lane & 8) ? 8 : 0;
    const int ntiles = (NE + 63) >> 6;

    for (int tile = blockIdx.x * 2 + g; tile < ntiles; tile += gridDim.x * 2) {
        BARG(bar);
        if (t8 < 64) {
            int e = tile * 64 + t8;
            ssrc[t8] = (e < NE) ? src[e] : -1;
            sdst[t8] = (e < NE) ? dst[e] : -1;
        }
        for (int i = t8; i < 64 * 8; i += 256) {
            int row = i >> 3, gg = i & 7, k0 = gg * 8;
            int e = tile * 64 + row;
            uint4 H = make_uint4(0, 0, 0, 0), L = H;
            if (e < NE) {
                float4 v0 = *(const float4*)(ea + (size_t)e * DE + k0);
                float4 v1 = *(const float4*)(ea + (size_t)e * DE + k0 + 4);
                splitp(v0.x, v0.y, H.x, L.x); splitp(v0.z, v0.w, H.y, L.y);
                splitp(v1.x, v1.y, H.z, L.z); splitp(v1.z, v1.w, H.w, L.w);
            }
            *(uint4*)(sm + AH + row * MP + gg * 16) = H;
            *(uint4*)(sm + AL + row * MP + gg * 16) = L;
        }
        BARG(bar);
        for (int i = t8; i < 64 * 32; i += 256) {
            int row = i >> 5, q = i & 31;
            int s = ssrc[row];
            if (s >= 0)
                *(float4*)(xws + row * 132 + q * 4) =
                    *(const float4*)(g_xw + (size_t)s * DN + q * 4);
        }
        BARG(bar);

        float c[8][4];
#pragma unroll
        for (int n = 0; n < 8; ++n) { c[n][0] = c[n][1] = c[n][2] = c[n][3] = 0.f; }
#pragma unroll
        for (int ks = 0; ks < 4; ++ks) {
            int k0 = ks * 16;
            uint32_t ah[4], al[4];
            uint32_t aoff = am * MP + (k0 + ak) * 2;
            LDSM4(ah[0], ah[1], ah[2], ah[3], sb + AH + aoff);
            LDSM4(al[0], al[1], al[2], al[3], sb + AL + aoff);
            uint32_t Bh[8][2], Bl[8][2];
#pragma unroll
            for (int p = 0; p < 4; ++p) {
                uint32_t boff = (uint32_t)(bn0 + p * 16) * MP + (k0 + bk) * 2;
                LDSM4(Bh[2 * p][0], Bh[2 * p][1], Bh[2 * p + 1][0], Bh[2 * p + 1][1],
                      sb + MS_WT_H + boff);
                LDSM4(Bl[2 * p][0], Bl[2 * p][1], Bl[2 * p + 1][0], Bl[2 * p + 1][1],
                      sb + MS_WT_L + boff);
            }
#pragma unroll
            for (int n = 0; n < 8; ++n) MMA(c[n], ah, Bh[n]);
#pragma unroll
            for (int n = 0; n < 8; ++n) MMA(c[n], ah, Bl[n]);
#pragma unroll
            for (int n = 0; n < 8; ++n) MMA(c[n], al, Bh[n]);
        }
        int r0 = we * 16 + (lane >> 2), r1 = r0 + 8;
        int d0 = sdst[r0], d1 = sdst[r1];
#pragma unroll
        for (int n = 0; n < 8; ++n) {
            int col = wo * 64 + n * 8 + (lane & 3) * 2;
            float b0 = bs[col], b1 = bs[col + 1];
            if (d0 >= 0) {
                float v0 = fmaxf(c[n][0] + xws[r0 * 132 + col] + b0, 0.f);
                float v1 = fmaxf(c[n][1] + xws[r0 * 132 + col + 1] + b1, 0.f);
                if (v0 > 0.f || v1 > 0.f)
                    RED2(g_agg + (size_t)d0 * DN + col, v0, v1);
            }
            if (d1 >= 0) {
                float v0 = fmaxf(c[n][2] + xws[r1 * 132 + col] + b0, 0.f);
                float v1 = fmaxf(c[n][3] + xws[r1 * 132 + col + 1] + b1, 0.f);
                if (v0 > 0.f || v1 > 0.f)
                    RED2(g_agg + (size_t)d1 * DN + col, v0, v1);
            }
        }
    }
}

// ============ EDGE: 256 thr single group, 3 blocks/SM (R12-proven) ============
#define EP 144
#define ED_WT_H 0
#define ED_WT_L 9216
#define ED_A_H 18432
#define ED_A_L 27648
#define ED_XE1 36864
#define ED_XE2 54272
#define ED_IDX 71680
#define ED_BIAS 72192
#define ED_SMEM 72448

__global__ void __launch_bounds__(256, 1)
edge_mma(const float* __restrict__ ea,
         const int* __restrict__ src, const int* __restrict__ dst,
         const float* __restrict__ W, const float* __restrict__ bias) {
    extern __shared__ char sm[];
    const uint32_t sb = smem_u32(sm);
    float* bs = (float*)(sm + ED_BIAS);
    float* xe1s = (float*)(sm + ED_XE1);
    float* xe2s = (float*)(sm + ED_XE2);
    int* ssrc = (int*)(sm + ED_IDX);
    int* sdst = ssrc + 64;
    const int t = threadIdx.x, lane = t & 31, wid = t >> 5;

    for (int i = t; i < 64 * 32; i += 256) {
        int n = i & 63, kp = i >> 6;
        uint32_t h, l;
        splitp(W[(2 * kp) * DE + n], W[(2 * kp + 1) * DE + n], h, l);
        *(uint32_t*)(sm + ED_WT_H + n * EP + kp * 4) = h;
        *(uint32_t*)(sm + ED_WT_L + n * EP + kp * 4) = l;
    }
    if (t < 64) bs[t] = bias[t];

    const int we = wid >> 1, wo = wid & 1;
    const int am = we * 16 + (lane & 15);
    const int ak = (lane >> 4) << 3;
    const int bn0 = wo * 32 + (lane & 7) + ((lane >> 4) << 3);
    const int bk = (lane & 8) ? 8 : 0;
    const int ntiles = (NE + 63) >> 6;

    for (int tile = blockIdx.x; tile < ntiles; tile += gridDim.x) {
        __syncthreads();
        if (t < 64) {
            int e = tile * 64 + t;
            ssrc[t] = (e < NE) ? src[e] : -1;
            sdst[t] = (e < NE) ? dst[e] : -1;
        }
        for (int i = t; i < 64 * 8; i += 256) {
            int row = i >> 3, gg = i & 7, k0 = gg * 8;
            int e = tile * 64 + row;
            uint4 H = make_uint4(0, 0, 0, 0), L = H;
            if (e < NE) {
                float4 v0 = *(const float4*)(ea + (size_t)e * DE + k0);
                float4 v1 = *(const float4*)(ea + (size_t)e * DE + k0 + 4);
                splitp(v0.x, v0.y, H.x, L.x); splitp(v0.z, v0.w, H.y, L.y);
                splitp(v1.x, v1.y, H.z, L.z); splitp(v1.z, v1.w, H.w, L.w);
            }
            *(uint4*)(sm + ED_A_H + row * EP + gg * 16) = H;
            *(uint4*)(sm + ED_A_L + row * EP + gg * 16) = L;
        }
        __syncthreads();
        for (int i = t; i < 64 * 16; i += 256) {
            int row = i >> 4, q = i & 15;
            int s = ssrc[row], d = sdst[row];
            if (s >= 0) {
                *(float4*)(xe1s + row * 68 + q * 4) =
                    *(const float4*)(g_xe + (size_t)s * DN + q * 4);
                *(float4*)(xe2s + row * 68 + q * 4) =
                    *(const float4*)(g_xe + (size_t)d * DN + 64 + q * 4);
            }
        }
        __syncthreads();

        float c[4][4];
#pragma unroll
        for (int n = 0; n < 4; ++n) { c[n][0] = c[n][1] = c[n][2] = c[n][3] = 0.f; }
#pragma unroll
        for (int ks = 0; ks < 4; ++ks) {
            int k0 = ks * 16;
            uint32_t ah[4], al[4];
            uint32_t aoff = am * EP + (k0 + ak) * 2;
            LDSM4(ah[0], ah[1], ah[2], ah[3], sb + ED_A_H + aoff);
            LDSM4(al[0], al[1], al[2], al[3], sb + ED_A_L + aoff);
            uint32_t Bh[4][2], Bl[4][2];
#pragma unroll
            for (int p = 0; p < 2; ++p) {
                uint32_t boff = (uint32_t)(bn0 + p * 16) * EP + (k0 + bk) * 2;
                LDSM4(Bh[2 * p][0], Bh[2 * p][1], Bh[2 * p + 1][0], Bh[2 * p + 1][1],
                      sb + ED_WT_H + boff);
                LDSM4(Bl[2 * p][0], Bl[2 * p][1], Bl[2 * p + 1][0], Bl[2 * p + 1][1],
                      sb + ED_WT_L + boff);
            }
#pragma unroll
            for (int n = 0; n < 4; ++n) MMA(c[n], ah, Bh[n]);
#pragma unroll
            for (int n = 0; n < 4; ++n) MMA(c[n], ah, Bl[n]);
#pragma unroll
            for (int n = 0; n < 4; ++n) MMA(c[n], al, Bh[n]);
        }
        int r0 = we * 16 + (lane >> 2), r1 = r0 + 8;
        int e0 = tile * 64 + r0, e1 = tile * 64 + r1;
#pragma unroll
        for (int n = 0; n < 4; ++n) {
            int col = wo * 32 + n * 8 + (lane & 3) * 2;
            float b0 = bs[col], b1 = bs[col + 1];
            if (e0 < NE) {
                float2 v = make_float2(
                    fmaxf(c[n][0] + xe1s[r0 * 68 + col] + xe2s[r0 * 68 + col] + b0, 0.f),
                    fmaxf(c[n][1] + xe1s[r0 * 68 + col + 1] + xe2s[r0 * 68 + col + 1] + b1, 0.f));
                *(float2*)(g_ea + (size_t)e0 * DE + col) = v;
            }
            if (e1 < NE) {
                float2 v = make_float2(
                    fmaxf(c[n][2] + xe1s[r1 * 68 + col] + xe2s[r1 * 68 + col] + b0, 0.f),
                    fmaxf(c[n][3] + xe1s[r1 * 68 + col + 1] + xe2s[r1 * 68 + col + 1] + b1, 0.f));
                *(float2*)(g_ea + (size_t)e1 * DE + col) = v;
            }
        }
    }
}

// ============ UPDATE (mma, 512 thr split-K; zeroes g_agg as it reads) ============
#define UP_P 528
#define UP_WT_H 0
#define UP_WT_L 67584
#define UP_A 135168
#define UP_BIAS 202752
#define UP_SINV 203264
#define UP_SSQ 203520
#define UP_SMEM 204032

__global__ void __launch_bounds__(512, 1)
upd_mma(const float* __restrict__ xin,
        const float* __restrict__ W, const float* __restrict__ bias) {
    extern __shared__ char sm[];
    const uint32_t sb = smem_u32(sm);
    float* bs = (float*)(sm + UP_BIAS);
    float* sinv = (float*)(sm + UP_SINV);
    float* ssq = (float*)(sm + UP_SSQ);
    float* P = (float*)(sm + UP_A);
    const int t = threadIdx.x, lane = t & 31, wid = t >> 5;
    const int wk = wid >> 3, w8 = wid & 7;

    for (int i = t; i < 128 * 128; i += 512) {
        int n = i & 127, kp = i >> 7;
        uint32_t h, l;
        splitp(W[(2 * kp) * DN + n], W[(2 * kp + 1) * DN + n], h, l);
        *(uint32_t*)(sm + UP_WT_H + n * UP_P + kp * 4) = h;
        *(uint32_t*)(sm + UP_WT_L + n * UP_P + kp * 4) = l;
    }
    if (t < 128) bs[t] = bias[t];

    const int we = w8 >> 1, wo = w8 & 1;
    const int am = we * 16 + (lane & 15);
    const int ak = (lane >> 4) << 3;
    const int bn0 = wo * 64 + (lane & 7) + ((lane >> 4) << 3);
    const int bk = (lane & 8) ? 8 : 0;
    const int ntiles = (NN + 63) >> 6;

    for (int tile = blockIdx.x; tile < ntiles; tile += gridDim.x) {
        __syncthreads();
        if (t < 64) {
            int i = (tile << 6) + t;
            float c = (i < NN) ? g_cnt[i] : 1.f;
            sinv[t] = 1.f / fmaxf(c, 1.f);
        }
        __syncthreads();
        for (int i = t; i < 64 * 32; i += 512) {
            int row = i >> 5, gg = i & 31, k0 = gg * 8;
            int nd = (tile << 6) + row;
            uint4 H = make_uint4(0, 0, 0, 0), L = H;
            if (nd < NN) {
                float4 v0, v1;
                if (k0 < DN) {
                    float iv = sinv[row];
                    v0 = *(const float4*)(g_agg + (size_t)nd * DN + k0);
                    v1 = *(const float4*)(g_agg + (size_t)nd * DN + k0 + 4);
                    // zero agg for the next layer's msg pass (replaces memset)
                    float4 z = make_float4(0.f, 0.f, 0.f, 0.f);
                    *(float4*)(g_agg + (size_t)nd * DN + k0) = z;
                    *(float4*)(g_agg + (size_t)nd * DN + k0 + 4) = z;
                    v0.x *= iv; v0.y *= iv; v0.z *= iv; v0.w *= iv;
                    v1.x *= iv; v1.y *= iv; v1.z *= iv; v1.w *= iv;
                } else {
                    v0 = *(const float4*)(xin + (size_t)nd * DN + (k0 - DN));
                    v1 = *(const float4*)(xin + (size_t)nd * DN + (k0 - DN) + 4);
                }
                splitp(v0.x, v0.y, H.x, L.x); splitp(v0.z, v0.w, H.y, L.y);
                splitp(v1.x, v1.y, H.z, L.z); splitp(v1.z, v1.w, H.w, L.w);
            }
            *(uint4*)(sm + UP_A + row * UP_P + gg * 16) = H;
            *(uint4*)(sm + UP_A + 33792 + row * UP_P + gg * 16) = L;
        }
        __syncthreads();

        float c[8][4];
#pragma unroll
        for (int n = 0; n < 8; ++n) { c[n][0] = c[n][1] = c[n][2] = c[n][3] = 0.f; }
#pragma unroll
        for (int j = 0; j < 8; ++j) {
            int k0 = (wk * 8 + j) * 16;
            uint32_t ah[4], al[4];
            uint32_t aoff = am * UP_P + (k0 + ak) * 2;
            LDSM4(ah[0], ah[1], ah[2], ah[3], sb + UP_A + aoff);
            LDSM4(al[0], al[1], al[2], al[3], sb + UP_A + 33792 + aoff);
            uint32_t Bh[8][2], Bl[8][2];
#pragma unroll
            for (int p = 0; p < 4; ++p) {
                uint32_t boff = (uint32_t)(bn0 + p * 16) * UP_P + (k0 + bk) * 2;
                LDSM4(Bh[2 * p][0], Bh[2 * p][1], Bh[2 * p + 1][0], Bh[2 * p + 1][1],
                      sb + UP_WT_H + boff);
                LDSM4(Bl[2 * p][0], Bl[2 * p][1], Bl[2 * p + 1][0], Bl[2 * p + 1][1],
                      sb + UP_WT_L + boff);
            }
#pragma unroll
            for (int n = 0; n < 8; ++n) MMA(c[n], ah, Bh[n]);
#pragma unroll
            for (int n = 0; n < 8; ++n) MMA(c[n], ah, Bl[n]);
#pragma unroll
            for (int n = 0; n < 8; ++n) MMA(c[n], al, Bh[n]);
        }
        __syncthreads();
        int r0 = we * 16 + (lane >> 2), r1 = r0 + 8;
        if (wk == 0) {
#pragma unroll
            for (int n = 0; n < 8; ++n) {
                int col = wo * 64 + n * 8 + (lane & 3) * 2;
                *(float2*)(P + r0 * 128 + col) = make_float2(c[n][0], c[n][1]);
                *(float2*)(P + r1 * 128 + col) = make_float2(c[n][2], c[n][3]);
            }
        }
        __syncthreads();
        if (wk == 1) {
            float s0 = 0.f, s1 = 0.f;
#pragma unroll
            for (int n = 0; n < 8; ++n) {
                int col = wo * 64 + n * 8 + (lane & 3) * 2;
                float b0 = bs[col], b1 = bs[col + 1];
                float2 p0 = *(float2*)(P + r0 * 128 + col);
                float2 p1 = *(float2*)(P + r1 * 128 + col);
                c[n][0] = fmaxf(c[n][0] + p0.x + b0, 0.f);
                c[n][1] = fmaxf(c[n][1] + p0.y + b1, 0.f);
                c[n][2] = fmaxf(c[n][2] + p1.x + b0, 0.f);
                c[n][3] = fmaxf(c[n][3] + p1.y + b1, 0.f);
                s0 += c[n][0] * c[n][0] + c[n][1] * c[n][1];
                s1 += c[n][2] * c[n][2] + c[n][3] * c[n][3];
            }
            s0 += __shfl_xor_sync(0xffffffffu, s0, 1);
            s0 += __shfl_xor_sync(0xffffffffu, s0, 2);
            s1 += __shfl_xor_sync(0xffffffffu, s1, 1);
            s1 += __shfl_xor_sync(0xffffffffu, s1, 2);
            if ((lane & 3) == 0) {
                ssq[wo * 64 + r0] = s0;
                ssq[wo * 64 + r1] = s1;
            }
        }
        __syncthreads();
        if (wk == 1) {
            float sc0 = 1.f / fmaxf(sqrtf(ssq[r0] + ssq[64 + r0]), 1e-12f);
            float sc1 = 1.f / fmaxf(sqrtf(ssq[r1] + ssq[64 + r1]), 1e-12f);
            int i0 = (tile << 6) + r0, i1 = (tile << 6) + r1;
#pragma unroll
            for (int n = 0; n < 8; ++n) {
                int col = wo * 64 + n * 8 + (lane & 3) * 2;
                if (i0 < NN)
                    *(float2*)(g_x + (size_t)i0 * DN + col) =
                        make_float2(c[n][0] * sc0, c[n][1] * sc0);
                if (i1 < NN)
                    *(float2*)(g_x + (size_t)i1 * DN + col) =
                        make_float2(c[n][2] * sc1, c[n][3] * sc1);
            }
        }
    }
}

// ===================== HEAD (SIMT, 256 thr, grid 2x) =====================
__global__ void __launch_bounds__(256, 2)
head_kernel(const float* __restrict__ W1, const float* __restrict__ b1,
            const float* __restrict__ W2, const float* __restrict__ b2,
            float* __restrict__ out) {
    extern __shared__ float smf[];
    float* W1s = smf;
    float* b1s = W1s + DN * HM;
    float* W2s = b1s + HM;
    float* b2s = W2s + HM * DN;
    float* ins = b2s + DN;
    float* hs = ins + 32 * DN;
    const int t = threadIdx.x;
    for (int i = t; i < DN * HM; i += 256) W1s[i] = W1[i];
    for (int i = t; i < HM * DN; i += 256) W2s[i] = W2[i];
    if (t < HM) b1s[t] = b1[t];
    if (t < DN) b2s[t] = b2[t];
    const int tx1 = t & 15, ty1 = t >> 4;
    const int tx2 = t & 31, ty2 = t >> 5;
    const int ntiles = (NN + 31) >> 5;
    for (int tile = blockIdx.x; tile < ntiles; tile += gridDim.x) {
        __syncthreads();
        for (int idx = t; idx < 32 * DN; idx += 256) {
            int it = idx >> 7, c = idx & 127;
            int i = (tile << 5) + it;
            ins[idx] = (i < NN) ? g_x[(size_t)i * DN + c] : 0.f;
        }
        __syncthreads();
        {
            float acc[2][4] = {{0, 0, 0, 0}, {0, 0, 0, 0}};
            const float* inp = ins + (ty1 * 2) * DN;
#pragma unroll 2
            for (int k = 0; k < DN; ++k) {
                float4 w = *(const float4*)(W1s + k * HM + 4 * tx1);
                float v0 = inp[k], v1 = inp[DN + k];
                acc[0][0] += v0 * w.x; acc[0][1] += v0 * w.y;
                acc[0][2] += v0 * w.z; acc[0][3] += v0 * w.w;
                acc[1][0] += v1 * w.x; acc[1][1] += v1 * w.y;
                acc[1][2] += v1 * w.z; acc[1][3] += v1 * w.w;
            }
#pragma unroll
            for (int jj = 0; jj < 2; ++jj) {
                int it = ty1 * 2 + jj;
#pragma unroll
                for (int c = 0; c < 4; ++c)
                    hs[it * HM + 4 * tx1 + c] = fmaxf(acc[jj][c] + b1s[4 * tx1 + c], 0.f);
            }
        }
        __syncthreads();
        {
            float acc[4][4];
#pragma unroll
            for (int ii = 0; ii < 4; ++ii)
#pragma unroll
                for (int c = 0; c < 4; ++c) acc[ii][c] = 0.f;
            const float* inp = hs + (ty2 * 4) * HM;
#pragma unroll 2
            for (int k = 0; k < HM; ++k) {
                float4 w = *(const float4*)(W2s + k * DN + 4 * tx2);
#pragma unroll
                for (int ii = 0; ii < 4; ++ii) {
                    float v = inp[ii * HM + k];
                    acc[ii][0] += v * w.x; acc[ii][1] += v * w.y;
                    acc[ii][2] += v * w.z; acc[ii][3] += v * w.w;
                }
            }
#pragma unroll
            for (int ii = 0; ii < 4; ++ii) {
                int i = (tile << 5) + ty2 * 4 + ii;
                if (i < NN) {
                    float* o = out + (size_t)i * DN + 4 * tx2;
#pragma unroll
                    for (int c = 0; c < 4; ++c) o[c] = acc[ii][c] + b2s[4 * tx2 + c];
                }
            }
        }
    }
}

// ===================== launch =====================
extern "C" void kernel_launch(void* const* d_in, const int* in_sizes, int n_in,
                              void* d_out, int out_size) {
    (void)in_sizes; (void)n_in; (void)out_size;
    const float* x  = (const float*)d_in[0];
    const float* ea = (const float*)d_in[1];
    const int*   ei = (const int*)d_in[2];
    const float* Wm = (const float*)d_in[3];
    const float* bm = (const float*)d_in[4];
    const float* Wa = (const float*)d_in[5];
    const float* ba = (const float*)d_in[6];
    const float* We = (const float*)d_in[7];
    const float* be = (const float*)d_in[8];
    const float* W1 = (const float*)d_in[9];
    const float* b1 = (const float*)d_in[10];
    const float* W2 = (const float*)d_in[11];
    const float* b2 = (const float*)d_in[12];
    float* out = (float*)d_out;
    const int* src = ei;
    const int* dst = ei + NE;

    int nsm = 0;
    cudaDeviceGetAttribute(&nsm, cudaDevAttrMultiProcessorCount, 0);
    if (nsm <= 0) nsm = 148;

    const int SM_HED = (DN * HM + HM + HM * DN + DN + 32 * DN + 32 * HM) * 4;

    cudaFuncSetAttribute(node_both, cudaFuncAttributeMaxDynamicSharedMemorySize, NB_SMEM);
    cudaFuncSetAttribute(msg_mma,  cudaFuncAttributeMaxDynamicSharedMemorySize, MS_SMEM);
    cudaFuncSetAttribute(edge_mma, cudaFuncAttributeMaxDynamicSharedMemorySize, ED_SMEM);
    cudaFuncSetAttribute(upd_mma,  cudaFuncAttributeMaxDynamicSharedMemorySize, UP_SMEM);
    cudaFuncSetAttribute(head_kernel, cudaFuncAttributeMaxDynamicSharedMemorySize, SM_HED);

    void *agg_addr = 0, *cnt_addr = 0, *x_addr = 0, *ea_addr = 0;
    void *xw_addr = 0, *xe_addr = 0;
    cudaGetSymbolAddress(&agg_addr, g_agg);
    cudaGetSymbolAddress(&cnt_addr, g_cnt);
    cudaGetSymbolAddress(&x_addr, g_x);
    cudaGetSymbolAddress(&ea_addr, g_ea);
    cudaGetSymbolAddress(&xw_addr, g_xw);
    cudaGetSymbolAddress(&xe_addr, g_xe);

    cudaMemsetAsync(cnt_addr, 0, NN * sizeof(float));
    cudaMemsetAsync(agg_addr, 0, (size_t)NN * DN * sizeof(float));  // once; upd re-zeroes
    cnt_kernel<<<(NE + 255) / 256, 256>>>(dst);

    node_both<<<nsm, 512, NB_SMEM>>>(x, We, Wm, 0, 1,
                                     (float*)xe_addr, (float*)xw_addr);

    for (int l = 0; l < 3; ++l) {
        const float* xl  = (l == 0) ? x  : (const float*)x_addr;
        const float* eal = (l == 0) ? ea : (const float*)ea_addr;
        const float* Wml = Wm + (size_t)l * (DN + DE) * DN;
        const float* Wel = We + (size_t)l * (2 * DN + DE) * DE;
        const float* Wmn = (l < 2) ? Wm + (size_t)(l + 1) * (DN + DE) * DN : Wm;
        msg_mma<<<nsm, 512, MS_SMEM>>>(eal, src, dst, Wml + 128 * DN, bm + l * DN);
        upd_mma<<<nsm, 512, UP_SMEM>>>(xl, Wa + (size_t)l * KA * DN, ba + l * DN);
        node_both<<<nsm, 512, NB_SMEM>>>((const float*)x_addr, Wel, Wmn,
                                         1, (l < 2) ? 1 : 0,
                                         (float*)xe_addr, (float*)xw_addr);
        edge_mma<<<3 * nsm, 256, ED_SMEM>>>(eal, src, dst, Wel + 256 * DE, be + l * DE);
    }
    head_kernel<<<2 * nsm, 256, SM_HED>>>(W1, b1, W2, b2, out);
}